// round 6
// baseline (speedup 1.0000x reference)
#include <cuda_runtime.h>

// Problem dims
#define NNODES 207
#define LT     12
#define CIN    32
#define COUT   32
#define BATCH  256
#define NPAIR  (BATCH*COUT)        // 8192 (n,o) pairs
#define COLSF  (NNODES*LT)         // 2484 floats per (n,c) slice
#define PCOLS  (COLSF/2)           // 1242 float2 per slice
#define XELEMS (BATCH*CIN*COLSF)   // 20,348,928
#define NSQ    (NNODES*NNODES)

typedef unsigned long long u64;
typedef unsigned int u32;

// Scratch (static device globals — no allocation).
__device__ float g_mats[3*NSQ];    // [0]=A, [1]=A2, [2]=M
__device__ float g_Y[XELEMS];      // channel-mixed intermediate, [n][o][w][l]

// ---- packed fp32x2 helpers ---------------------------------------------
__device__ __forceinline__ u64 pack2(float x) {
    u64 r; asm("mov.b64 %0, {%1, %1};" : "=l"(r) : "f"(x)); return r;
}
__device__ __forceinline__ void ffma2(u64 &d, u64 a, u64 b) {
    asm("fma.rn.f32x2 %0, %1, %2, %0;" : "+l"(d) : "l"(a), "l"(b));
}
__device__ __forceinline__ u64 add2(u64 a, u64 b) {
    u64 r; asm("add.rn.f32x2 %0, %1, %2;" : "=l"(r) : "l"(a), "l"(b)); return r;
}

// ---- K0a: row-normalized A = (adj + I) / rowsum ------------------------
__global__ void k_norm(const float* __restrict__ adj) {
    int v = blockIdx.x;
    __shared__ float red[256];
    float s = 0.f;
    for (int w = threadIdx.x; w < NNODES; w += 256)
        s += adj[v*NNODES + w] + (w == v ? 1.f : 0.f);
    red[threadIdx.x] = s;
    __syncthreads();
    for (int st = 128; st > 0; st >>= 1) {
        if (threadIdx.x < st) red[threadIdx.x] += red[threadIdx.x + st];
        __syncthreads();
    }
    float inv = 1.f / red[0];
    for (int w = threadIdx.x; w < NNODES; w += 256)
        g_mats[v*NNODES + w] = (adj[v*NNODES + w] + (w == v ? 1.f : 0.f)) * inv;
}

// ---- K0b: A2 = A @ A ---------------------------------------------------
__global__ void k_A2() {
    int v = blockIdx.x, u = threadIdx.x;
    if (u >= NNODES) return;
    const float* A = g_mats;
    float acc = 0.f;
    for (int w = 0; w < NNODES; w++)
        acc += A[v*NNODES + w] * A[w*NNODES + u];
    g_mats[NSQ + v*NNODES + u] = acc;
}

// ---- K0c: M = AL*I + c1*A + c2*A2 + c3*(A2@A) --------------------------
__global__ void k_M() {
    const float AL = 0.05f, BE = 0.95f;
    const float c1 = AL*BE, c2 = AL*BE*BE, c3 = BE*BE*BE;
    int v = blockIdx.x, u = threadIdx.x;
    if (u >= NNODES) return;
    const float* A  = g_mats;
    const float* A2 = g_mats + NSQ;
    float acc = 0.f;
    for (int w = 0; w < NNODES; w++)
        acc += A2[v*NNODES + w] * A[w*NNODES + u];
    float r = c3*acc + c2*A2[v*NNODES + u] + c1*A[v*NNODES + u]
            + (u == v ? AL : 0.f);
    g_mats[2*NSQ + v*NNODES + u] = r;
}

// ---- K1: channel mix  Y[n,o,w,l] = sum_c W[o,c] x[n,c,w,l] -------------
// o-split: 256 thr = 64 pc x 4 o-groups, 8 accumulators/thread -> high occ.
// The 4 groups re-read the same x line (L1-served after first).
__global__ __launch_bounds__(256) void k_cmix(const float* __restrict__ x,
                                              const float* __restrict__ W) {
    __shared__ u64 Ws2[CIN][COUT];   // [c][o], value duplicated in both halves
    int n   = blockIdx.y;
    int t   = threadIdx.x;
    int og  = t >> 6;                // 0..3 (8 outputs each)
    int pcl = t & 63;
    int pc  = blockIdx.x * 64 + pcl;

    for (int i = t; i < CIN*COUT; i += 256) {
        int o = i >> 5, c = i & 31;
        Ws2[c][o] = pack2(W[i]);     // W layout (COUT, CIN)
    }
    __syncthreads();
    if (pc >= PCOLS) return;

    const u64* xp = (const u64*)x + (size_t)n*CIN*PCOLS + pc;

    u64 acc[8];
#pragma unroll
    for (int j = 0; j < 8; j++) acc[j] = 0ull;
#pragma unroll 4
    for (int c = 0; c < CIN; c++) {
        u64 xv = xp[(size_t)c * PCOLS];
#pragma unroll
        for (int j = 0; j < 8; j++) ffma2(acc[j], Ws2[c][og*8 + j], xv);
    }
    u64* y2 = (u64*)g_Y + (size_t)n*COUT*PCOLS + (size_t)(og*8)*PCOLS + pc;
#pragma unroll
    for (int j = 0; j < 8; j++)
        y2[(size_t)j * PCOLS] = acc[j];
}

// ---- K2: node GEMM  out[n,o,v,l] = sum_w M[v,w] Y[n,o,w,l] + b[o] ------
// Thread tile 4v x 3 packed cols (24 acc regs) -> 3 CTAs/SM.
#define VT 32    // v-rows per block (7 tiles cover 207)
#define GP 16    // (n,o) pairs per block (cols = GP*6 = 96 u64)
#define KC 16    // k chunk
#define YROW 98  // padded Ysh row length in u64
__global__ __launch_bounds__(256, 3) void k_node(const float* __restrict__ b,
                                                 float* __restrict__ out) {
    __shared__ u64 Ms2[VT][KC];      // 4 KB: M[v][w] duplicated (m,m)
    __shared__ u64 Ysh[KC][YROW];    // 12.25 KB
    int v0  = blockIdx.x * VT;
    int pb  = blockIdx.y * GP;
    int tid = threadIdx.x;
    int ty  = tid >> 5, tx = tid & 31;   // ty: 4 v's each, tx: 3 cols

    u64 acc[4][3];
#pragma unroll
    for (int j = 0; j < 4; j++)
#pragma unroll
        for (int i = 0; i < 3; i++) acc[j][i] = 0ull;

    const u64*  yg = (const u64*)g_Y;
    const float* M = g_mats + 2*NSQ;
    u64* ysh = &Ysh[0][0];

    // Precompute staging offsets once (6 Y-loads per thread per chunk).
    u32 gofs[6], sofs[6];
    int kkj[6];
#pragma unroll
    for (int j = 0; j < 6; j++) {
        int i   = tid + 256*j;         // 0..1535
        int p   = i / 96, r = i % 96;  // pair, (kk,pcz)
        int kk  = r / 6,  pcz = r % 6;
        kkj[j]  = kk;
        gofs[j] = (u32)((pb + p)*PCOLS + kk*6 + pcz);
        sofs[j] = (u32)(kk*YROW + p*6 + pcz);
    }
    // M staging coords (2 elems per thread)
    int mvl = tid >> 3;
    int mk2 = (tid & 7) * 2;
    int mv  = v0 + mvl;

    for (int w0 = 0; w0 < NNODES; w0 += KC) {
        // stage M tile (duplicated): VT*KC = 512 elems
#pragma unroll
        for (int jj = 0; jj < 2; jj++) {
            int w = w0 + mk2 + jj;
            float m = (mv < NNODES && w < NNODES) ? M[mv*NNODES + w] : 0.f;
            Ms2[mvl][mk2 + jj] = pack2(m);
        }
        // stage Y chunk: GP*KC*6 = 1536 u64, 6 per thread
#pragma unroll
        for (int j = 0; j < 6; j++) {
            bool ok = (w0 + kkj[j]) < NNODES;
            ysh[sofs[j]] = ok ? yg[gofs[j]] : 0ull;
            gofs[j] += KC*6;
        }
        __syncthreads();
#pragma unroll
        for (int kk = 0; kk < KC; kk++) {
            u64 yv[3];
#pragma unroll
            for (int i = 0; i < 3; i++) yv[i] = Ysh[kk][tx + 32*i];
#pragma unroll
            for (int j = 0; j < 4; j++) {
                u64 m2 = Ms2[ty*4 + j][kk];
#pragma unroll
                for (int i = 0; i < 3; i++) ffma2(acc[j][i], m2, yv[i]);
            }
        }
        __syncthreads();
    }

    // epilogue: add bias, store packed (v,l) runs
    u64* o2 = (u64*)out;
#pragma unroll
    for (int i = 0; i < 3; i++) {
        int pcol = tx + 32*i;
        int p = pcol / 6, pcz = pcol % 6;
        int pair = pb + p;
        u64 b2 = pack2(b[pair & 31]);
#pragma unroll
        for (int j = 0; j < 4; j++) {
            int v = v0 + ty*4 + j;
            if (v < NNODES)
                o2[(size_t)pair*PCOLS + (size_t)v*6 + pcz] = add2(acc[j][i], b2);
        }
    }
}

extern "C" void kernel_launch(void* const* d_in, const int* in_sizes, int n_in,
                              void* d_out, int out_size) {
    const float* x   = (const float*)d_in[0];
    const float* adj = (const float*)d_in[1];
    const float* W   = (const float*)d_in[2];
    const float* b   = (const float*)d_in[3];
    float* out = (float*)d_out;

    k_norm<<<NNODES, 256>>>(adj);
    k_A2 <<<NNODES, 224>>>();
    k_M  <<<NNODES, 224>>>();
    k_cmix<<<dim3((PCOLS + 63)/64, BATCH), 256>>>(x, W);
    k_node<<<dim3((NNODES + VT - 1)/VT, NPAIR/GP), 256>>>(b, out);
}